// round 9
// baseline (speedup 1.0000x reference)
#include <cuda_runtime.h>
#include <cstdint>

#define B_SZ  2
#define GQ    32
#define HDIM  128
#define NH    8
#define DK    16
#define SLEN  4096
#define STILE 8
#define NT    256

typedef unsigned long long u64;

// Warp roles: 8 warps, w = (sq | fq<<1): sq = s-quad (4 s = s-pairs spin0/spin1),
// fq = f-quarter (8 f) in logits, d-quarter (4 d) in the x phase. lane = g.
//
// SMEM (u64 units), total 14336 u64 = 114688 B -> 2 CTAs/SM:
//  sQ   [0,2048)      u64[((d*2+sq)*32+g)*2 + spin]  PRESCALED q (B5->B2 live)
//    eX  overlay [0,4096)  u64[((f*2+sq)*32+g)*2 + spin]  unnormalized exp (B2->B4)
//    xSt overlay [0,2048)  u64[(sp*16+d)*32 + g]          x staging (B4->B5)
//  sK   [2048,4096)   float[f*128 + d*8 + s]   (cp.async; live B1->B2)
//  sV   [4096,6144)   same                     (live B1->B4)
//  sL   [6144,10240)  u64[((f*2+sq)*32+g)*2 + spin]  logits sums over h
//  sA   [10240,14336) same                           attn sums over h
#define SQ_U64   0
#define SK_U64   2048
#define SV_U64   4096
#define SL_U64   6144
#define SA_U64   10240
#define SM_U64_TOTAL 14336
#define SM_BYTES (SM_U64_TOTAL * 8)   // 114688

// ---- packed f32x2 + misc helpers ----
__device__ __forceinline__ u64 pk2(float lo, float hi) {
    u64 r; asm("mov.b64 %0, {%1, %2};" : "=l"(r) : "f"(lo), "f"(hi)); return r;
}
__device__ __forceinline__ void up2(u64 v, float& lo, float& hi) {
    asm("mov.b64 {%0, %1}, %2;" : "=f"(lo), "=f"(hi) : "l"(v));
}
__device__ __forceinline__ u64 fma2(u64 a, u64 b, u64 c) {
    u64 d; asm("fma.rn.f32x2 %0, %1, %2, %3;" : "=l"(d) : "l"(a), "l"(b), "l"(c)); return d;
}
__device__ __forceinline__ u64 add2(u64 a, u64 b) {
    u64 d; asm("add.rn.f32x2 %0, %1, %2;" : "=l"(d) : "l"(a), "l"(b)); return d;
}
__device__ __forceinline__ u64 mul2(u64 a, u64 b) {
    u64 d; asm("mul.rn.f32x2 %0, %1, %2;" : "=l"(d) : "l"(a), "l"(b)); return d;
}
__device__ __forceinline__ float ex2a(float x) {
    float r; asm("ex2.approx.ftz.f32 %0, %1;" : "=f"(r) : "f"(x)); return r;
}
__device__ __forceinline__ float rcpa(float x) {
    float r; asm("rcp.approx.ftz.f32 %0, %1;" : "=f"(r) : "f"(x)); return r;
}
__device__ __forceinline__ void cp_async16(void* dst, const void* src) {
    unsigned sdst = (unsigned)__cvta_generic_to_shared(dst);
    asm volatile("cp.async.cg.shared.global [%0], [%1], 16;" :: "r"(sdst), "l"(src));
}
__device__ __forceinline__ void cp_commit() {
    asm volatile("cp.async.commit_group;" ::: "memory");
}
__device__ __forceinline__ void cp_wait0() {
    asm volatile("cp.async.wait_group 0;" ::: "memory");
}

// stage a 32x16x8-float tile (K or V): 1024 16B chunks, 4 per thread (NT=256)
__device__ __forceinline__ void stage_async(float* dst, const float* src0, int t) {
    #pragma unroll
    for (int i = 0; i < 4; ++i) {
        int c = t + NT * i;                     // chunk id 0..1023
        int r = c >> 1;                         // row = g*16 + d
        const float* src = src0 + ((size_t)(r >> 4) * HDIM + (r & 15)) * SLEN + 4 * (c & 1);
        cp_async16(dst + 4 * c, src);
    }
}

// Q staging by threads t<128 (lane = g row, w4 = warp in [0,4) = d offset)
__device__ __forceinline__ void load_q_ldg(ulonglong2* qA, ulonglong2* qB,
                                           const float* gq, int lane, int w4) {
    #pragma unroll
    for (int i = 0; i < 4; ++i) {
        int d = w4 + 4 * i;
        const float* src = gq + ((size_t)lane * HDIM + d) * SLEN;
        qA[i] = *(const ulonglong2*)(src);        // s0..3  (sq=0 slot)
        qB[i] = *(const ulonglong2*)(src + 4);    // s4..7  (sq=1 slot)
    }
}
// prescaled STS: q * (dk^-0.5 * log2e), layout ((d*2+sq)*32+g)*2+spin
__device__ __forceinline__ void sts_q(u64* sQ, const ulonglong2* qA, const ulonglong2* qB,
                                      int lane, int w4, u64 sc) {
    #pragma unroll
    for (int i = 0; i < 4; ++i) {
        int d = w4 + 4 * i;
        ulonglong2 a; a.x = mul2(qA[i].x, sc); a.y = mul2(qA[i].y, sc);
        ulonglong2 b; b.x = mul2(qB[i].x, sc); b.y = mul2(qB[i].y, sc);
        *(ulonglong2*)(sQ + ((size_t)(d * 2 + 0) * 32 + lane) * 2) = a;
        *(ulonglong2*)(sQ + ((size_t)(d * 2 + 1) * 32 + lane) * 2) = b;
    }
}

__global__ void __launch_bounds__(NT, 2)
sdpa_group_kernel(const float* __restrict__ q, const float* __restrict__ k,
                  const float* __restrict__ v, float* __restrict__ out)
{
    extern __shared__ u64 sm[];
    u64*   sQ  = sm + SQ_U64;
    u64*   eX  = sm + SQ_U64;      // overlay [0,4096): live B2->B4
    u64*   xSt = sm + SQ_U64;      // overlay [0,2048): live B4->B5
    float* sK  = (float*)(sm + SK_U64);
    float* sV  = (float*)(sm + SV_U64);
    u64*   sL  = sm + SL_U64;
    u64*   sA  = sm + SA_U64;

    const int t    = threadIdx.x;
    const int g    = t & 31;
    const int warp = t >> 5;
    const int sq   = warp & 1;           // s-quad: local s in [4sq, 4sq+4)
    const int fq   = warp >> 1;          // f-quarter (logits) / d-quarter (x)
    const int s0   = blockIdx.x * STILE;
    const int b    = blockIdx.y;
    const bool qstager = (t < 128);
    const int w4 = warp & 3;             // d-offset role for q staging (warps 0..3)

    const size_t base = (size_t)b * (GQ * HDIM) * SLEN + (size_t)s0;
    const float L2E = 1.4426950408889634f;
    const u64 sc = pk2(0.25f * L2E, 0.25f * L2E);

    // ---- prologue ----
    stage_async(sK, k + base, t);
    stage_async(sV, v + base, t);
    cp_commit();
    ulonglong2 qA[4], qB[4];
    if (qstager) load_q_ldg(qA, qB, q + base, g, w4);
    #pragma unroll 4
    for (int i = t; i < 8192; i += NT) sL[i] = 0ull;     // sL,sA contiguous
    if (qstager) sts_q(sQ, qA, qB, g, w4, sc);

    #pragma unroll 1
    for (int h = 0; h < NH; ++h) {
        cp_wait0();
        __syncthreads();         // B1: K,V,Q(h) visible; xSt consumed

        if (qstager && h < NH - 1)
            load_q_ldg(qA, qB, q + base + (size_t)(h + 1) * DK * SLEN, g, w4);

        // ---- logits for (8 f) x (4 s), log2 domain, 2 d-passes ----
        u64 lg0[8], lg1[8];      // [fi][spin]
        #pragma unroll
        for (int pass = 0; pass < 2; ++pass) {
            ulonglong2 qvh[8];
            #pragma unroll
            for (int dd = 0; dd < 8; ++dd) {
                int d = pass * 8 + dd;
                qvh[dd] = *(const ulonglong2*)(sQ + ((size_t)(d * 2 + sq) * 32 + g) * 2);
            }
            #pragma unroll
            for (int fi = 0; fi < 8; ++fi) {
                const float* kb = sK + (8 * fq + fi) * 128 + pass * 64 + 4 * sq;
                #pragma unroll
                for (int dd = 0; dd < 8; ++dd) {
                    ulonglong2 kk = *(const ulonglong2*)(kb + dd * 8);
                    if (pass == 0 && dd == 0) {
                        lg0[fi] = mul2(qvh[0].x, kk.x);
                        lg1[fi] = mul2(qvh[0].y, kk.y);
                    } else {
                        lg0[fi] = fma2(qvh[dd].x, kk.x, lg0[fi]);
                        lg1[fi] = fma2(qvh[dd].y, kk.y, lg1[fi]);
                    }
                }
            }
        }

        // ---- accumulate logits sums (paired u128 RMW) + exp2 ----
        #pragma unroll
        for (int fi = 0; fi < 8; ++fi) {
            int idx = (((8 * fq + fi) * 2 + sq) * 32 + g) * 2;
            ulonglong2* p = (ulonglong2*)(sL + idx);
            ulonglong2 c = *p;
            c.x = add2(c.x, lg0[fi]);
            c.y = add2(c.y, lg1[fi]);
            *p = c;
            float a, bb;
            up2(lg0[fi], a, bb); lg0[fi] = pk2(ex2a(a), ex2a(bb));
            up2(lg1[fi], a, bb); lg1[fi] = pk2(ex2a(a), ex2a(bb));
        }

        __syncthreads();         // B2: logits done everywhere (sQ, sK dead)

        // ---- post unnormalized exps to eX ----
        #pragma unroll
        for (int fi = 0; fi < 8; ++fi) {
            int idx = (((8 * fq + fi) * 2 + sq) * 32 + g) * 2;
            ulonglong2 e; e.x = lg0[fi]; e.y = lg1[fi];
            *(ulonglong2*)(eX + idx) = e;
        }
        __syncthreads();         // B3: all exps posted

        // ---- x phase: own d-quarter (4 d) x (4 s), all 32 f; lazy normalize ----
        u64 xv0[4], xv1[4], sum0, sum1;
        {
            const int dbase = 4 * fq;
            #pragma unroll
            for (int f = 0; f < GQ; ++f) {
                ulonglong2 p2 = *(const ulonglong2*)(eX + ((f * 2 + sq) * 32 + g) * 2);
                const float* vb = sV + f * 128 + dbase * 8 + 4 * sq;
                if (f == 0) {
                    sum0 = p2.x; sum1 = p2.y;
                    #pragma unroll
                    for (int dd = 0; dd < 4; ++dd) {
                        ulonglong2 vv = *(const ulonglong2*)(vb + dd * 8);
                        xv0[dd] = mul2(p2.x, vv.x);
                        xv1[dd] = mul2(p2.y, vv.y);
                    }
                } else {
                    sum0 = add2(sum0, p2.x); sum1 = add2(sum1, p2.y);
                    #pragma unroll
                    for (int dd = 0; dd < 4; ++dd) {
                        ulonglong2 vv = *(const ulonglong2*)(vb + dd * 8);
                        xv0[dd] = fma2(p2.x, vv.x, xv0[dd]);
                        xv1[dd] = fma2(p2.y, vv.y, xv1[dd]);
                    }
                }
            }
        }
        float ra, rb;
        up2(sum0, ra, rb); const u64 rn0 = pk2(rcpa(ra), rcpa(rb));
        up2(sum1, ra, rb); const u64 rn1 = pk2(rcpa(ra), rcpa(rb));
        #pragma unroll
        for (int dd = 0; dd < 4; ++dd) {
            xv0[dd] = mul2(xv0[dd], rn0);
            xv1[dd] = mul2(xv1[dd], rn1);
        }

        // ---- accumulate attn sums for own f-quarter (re-read eX, normalize) ----
        #pragma unroll
        for (int fi = 0; fi < 8; ++fi) {
            int idx = (((8 * fq + fi) * 2 + sq) * 32 + g) * 2;
            ulonglong2 pe = *(const ulonglong2*)(eX + idx);
            ulonglong2* pa = (ulonglong2*)(sA + idx);
            ulonglong2 c = *pa;
            c.x = add2(c.x, mul2(pe.x, rn0));
            c.y = add2(c.y, mul2(pe.y, rn1));
            *pa = c;
        }
        __syncthreads();         // B4: eX + sV dead everywhere

        // prefetch K(h+1), V(h+1)
        if (h < NH - 1) {
            stage_async(sK, k + base + (size_t)(h + 1) * DK * SLEN, t);
            stage_async(sV, v + base + (size_t)(h + 1) * DK * SLEN, t);
            cp_commit();
        }

        // ---- stage x into xSt [(sp*16+d)*32+g] ----
        #pragma unroll
        for (int dd = 0; dd < 4; ++dd) {
            int d = 4 * fq + dd;
            xSt[((2 * sq + 0) * 16 + d) * 32 + g] = xv0[dd];
            xSt[((2 * sq + 1) * 16 + d) * 32 + g] = xv1[dd];
        }
        __syncthreads();         // B4.5: x staged

        // ---- cooperative coalesced STG (32B per (g,d) row, 2 lanes/row) ----
        #pragma unroll
        for (int i = 0; i < 4; ++i) {
            int u    = t + NT * i;        // 0..1023 units of 16B
            int r    = u >> 1;
            int half = u & 1;
            int dd   = r >> 5;
            int g2   = r & 31;
            u64 lo = xSt[((2 * half)     * 16 + dd) * 32 + g2];
            u64 hi = xSt[((2 * half + 1) * 16 + dd) * 32 + g2];
            float* dst = out + ((size_t)((b * GQ + g2) * HDIM) + (size_t)h * DK + dd) * SLEN
                             + (size_t)s0 + 4 * half;
            ulonglong2 val; val.x = lo; val.y = hi;
            *(ulonglong2*)dst = val;
        }
        __syncthreads();         // B5: xSt reads done -> sQ region writable

        if (qstager && h < NH - 1) sts_q(sQ, qA, qB, g, w4, sc);
    }

    // ---- writeout head means ----
    __syncthreads();
    const size_t AOFF = (size_t)B_SZ * GQ * HDIM * SLEN;       // 33554432
    const size_t LOFF = AOFF + (size_t)B_SZ * GQ * GQ * SLEN;  // 41943040
    const u64 cA = pk2(0.125f, 0.125f);
    const float lsc = 0.125f / L2E;                            // undo log2-domain
    const u64 cL = pk2(lsc, lsc);
    #pragma unroll
    for (int i = 0; i < 4; ++i) {
        int r  = t + NT * i;      // 0..1023
        int f  = r & 31;
        int gg = r >> 5;
        size_t o = ((size_t)(b * GQ + gg) * GQ + f) * SLEN + (size_t)s0;
        #pragma unroll
        for (int sp2 = 0; sp2 < 4; ++sp2) {
            int idx = ((f * 2 + (sp2 >> 1)) * 32 + gg) * 2 + (sp2 & 1);
            *(u64*)(out + AOFF + o + 2 * sp2) = mul2(sA[idx], cA);
            *(u64*)(out + LOFF + o + 2 * sp2) = mul2(sL[idx], cL);
        }
    }
}

extern "C" void kernel_launch(void* const* d_in, const int* in_sizes, int n_in,
                              void* d_out, int out_size)
{
    const float* q = (const float*)d_in[0];
    const float* k = (const float*)d_in[1];
    const float* v = (const float*)d_in[2];
    float* out = (float*)d_out;

    cudaFuncSetAttribute(sdpa_group_kernel,
                         cudaFuncAttributeMaxDynamicSharedMemorySize, SM_BYTES);

    dim3 grid(SLEN / STILE, B_SZ);
    sdpa_group_kernel<<<grid, NT, SM_BYTES>>>(q, k, v, out);
}

// round 10
// speedup vs baseline: 1.0072x; 1.0072x over previous
#include <cuda_runtime.h>
#include <cstdint>

#define B_SZ  2
#define GQ    32
#define HDIM  128
#define NH    8
#define DK    16
#define SLEN  4096
#define STILE 8
#define NT    256

typedef unsigned long long u64;

// Warp roles: 8 warps, w = (sq | fq<<1): sq = s-quad (4 s = s-pairs spin0/spin1),
// fq = f-quarter (8 f) in logits, d-quarter (4 d) in the x phase. lane = g.
//
// SMEM (u64 units), total 14336 u64 = 114688 B -> 2 CTAs/SM:
//  sQ   [0,2048)      u64[((d*2+sq)*32+g)*2 + spin]  PRESCALED q (B5->B2 live)
//    eX  overlay [0,4096)  u64[((f*2+sq)*32+g)*2 + spin]  unnormalized exp (B2->B4)
//    xSt overlay [0,2048)  u64[(sp*16+d)*32 + g]          x staging (B4->B5)
//  sK   [2048,4096)   float[f*128 + d*8 + s]   (cp.async; live B1->B2)
//  sV   [4096,6144)   same                     (live B1->B4)
//  sL   [6144,10240)  u64[((f*2+sq)*32+g)*2 + spin]  logits sums over h
//  sA   [10240,14336) same                           attn sums over h
#define SQ_U64   0
#define SK_U64   2048
#define SV_U64   4096
#define SL_U64   6144
#define SA_U64   10240
#define SM_U64_TOTAL 14336
#define SM_BYTES (SM_U64_TOTAL * 8)   // 114688

// ---- packed f32x2 + misc helpers ----
__device__ __forceinline__ u64 pk2(float lo, float hi) {
    u64 r; asm("mov.b64 %0, {%1, %2};" : "=l"(r) : "f"(lo), "f"(hi)); return r;
}
__device__ __forceinline__ void up2(u64 v, float& lo, float& hi) {
    asm("mov.b64 {%0, %1}, %2;" : "=f"(lo), "=f"(hi) : "l"(v));
}
__device__ __forceinline__ u64 fma2(u64 a, u64 b, u64 c) {
    u64 d; asm("fma.rn.f32x2 %0, %1, %2, %3;" : "=l"(d) : "l"(a), "l"(b), "l"(c)); return d;
}
__device__ __forceinline__ u64 add2(u64 a, u64 b) {
    u64 d; asm("add.rn.f32x2 %0, %1, %2;" : "=l"(d) : "l"(a), "l"(b)); return d;
}
__device__ __forceinline__ u64 mul2(u64 a, u64 b) {
    u64 d; asm("mul.rn.f32x2 %0, %1, %2;" : "=l"(d) : "l"(a), "l"(b)); return d;
}
__device__ __forceinline__ float ex2a(float x) {
    float r; asm("ex2.approx.ftz.f32 %0, %1;" : "=f"(r) : "f"(x)); return r;
}
__device__ __forceinline__ float rcpa(float x) {
    float r; asm("rcp.approx.ftz.f32 %0, %1;" : "=f"(r) : "f"(x)); return r;
}
__device__ __forceinline__ void cp_async16(void* dst, const void* src) {
    unsigned sdst = (unsigned)__cvta_generic_to_shared(dst);
    asm volatile("cp.async.cg.shared.global [%0], [%1], 16;" :: "r"(sdst), "l"(src));
}
__device__ __forceinline__ void cp_commit() {
    asm volatile("cp.async.commit_group;" ::: "memory");
}
__device__ __forceinline__ void cp_wait0() {
    asm volatile("cp.async.wait_group 0;" ::: "memory");
}

// stage a 32x16x8-float tile (K or V): 1024 16B chunks, 4 per thread (NT=256)
__device__ __forceinline__ void stage_async(float* dst, const float* src0, int t) {
    #pragma unroll
    for (int i = 0; i < 4; ++i) {
        int c = t + NT * i;                     // chunk id 0..1023
        int r = c >> 1;                         // row = g*16 + d
        const float* src = src0 + ((size_t)(r >> 4) * HDIM + (r & 15)) * SLEN + 4 * (c & 1);
        cp_async16(dst + 4 * c, src);
    }
}

// Q staging by threads t<128 (lane = g row, w4 = warp in [0,4) = d offset)
__device__ __forceinline__ void load_q_ldg(ulonglong2* qA, ulonglong2* qB,
                                           const float* gq, int lane, int w4) {
    #pragma unroll
    for (int i = 0; i < 4; ++i) {
        int d = w4 + 4 * i;
        const float* src = gq + ((size_t)lane * HDIM + d) * SLEN;
        qA[i] = *(const ulonglong2*)(src);        // s0..3  (sq=0 slot)
        qB[i] = *(const ulonglong2*)(src + 4);    // s4..7  (sq=1 slot)
    }
}
// prescaled STS: q * (dk^-0.5 * log2e), layout ((d*2+sq)*32+g)*2+spin
__device__ __forceinline__ void sts_q(u64* sQ, const ulonglong2* qA, const ulonglong2* qB,
                                      int lane, int w4, u64 sc) {
    #pragma unroll
    for (int i = 0; i < 4; ++i) {
        int d = w4 + 4 * i;
        ulonglong2 a; a.x = mul2(qA[i].x, sc); a.y = mul2(qA[i].y, sc);
        ulonglong2 b; b.x = mul2(qB[i].x, sc); b.y = mul2(qB[i].y, sc);
        *(ulonglong2*)(sQ + ((size_t)(d * 2 + 0) * 32 + lane) * 2) = a;
        *(ulonglong2*)(sQ + ((size_t)(d * 2 + 1) * 32 + lane) * 2) = b;
    }
}

__global__ void __launch_bounds__(NT, 2)
sdpa_group_kernel(const float* __restrict__ q, const float* __restrict__ k,
                  const float* __restrict__ v, float* __restrict__ out)
{
    extern __shared__ u64 sm[];
    u64*   sQ  = sm + SQ_U64;
    u64*   eX  = sm + SQ_U64;      // overlay [0,4096): live B2->B4
    u64*   xSt = sm + SQ_U64;      // overlay [0,2048): live B4->B5
    float* sK  = (float*)(sm + SK_U64);
    float* sV  = (float*)(sm + SV_U64);
    u64*   sL  = sm + SL_U64;
    u64*   sA  = sm + SA_U64;

    const int t    = threadIdx.x;
    const int g    = t & 31;
    const int warp = t >> 5;
    const int sq   = warp & 1;           // s-quad: local s in [4sq, 4sq+4)
    const int fq   = warp >> 1;          // f-quarter (logits) / d-quarter (x)
    const int s0   = blockIdx.x * STILE;
    const int b    = blockIdx.y;
    const bool qstager = (t < 128);
    const int w4 = warp & 3;             // d-offset role for q staging (warps 0..3)

    const size_t base = (size_t)b * (GQ * HDIM) * SLEN + (size_t)s0;
    const float L2E = 1.4426950408889634f;
    const u64 sc = pk2(0.25f * L2E, 0.25f * L2E);

    // ---- prologue ----
    stage_async(sK, k + base, t);
    stage_async(sV, v + base, t);
    cp_commit();
    ulonglong2 qA[4], qB[4];
    if (qstager) load_q_ldg(qA, qB, q + base, g, w4);
    #pragma unroll 4
    for (int i = t; i < 8192; i += NT) sL[i] = 0ull;     // sL,sA contiguous
    if (qstager) sts_q(sQ, qA, qB, g, w4, sc);

    #pragma unroll 1
    for (int h = 0; h < NH; ++h) {
        cp_wait0();
        __syncthreads();         // B1: K,V,Q(h) visible; xSt consumed

        if (qstager && h < NH - 1)
            load_q_ldg(qA, qB, q + base + (size_t)(h + 1) * DK * SLEN, g, w4);

        // ---- logits for (8 f) x (4 s), log2 domain, 2 d-passes ----
        u64 lg0[8], lg1[8];      // [fi][spin]
        #pragma unroll
        for (int pass = 0; pass < 2; ++pass) {
            ulonglong2 qvh[8];
            #pragma unroll
            for (int dd = 0; dd < 8; ++dd) {
                int d = pass * 8 + dd;
                qvh[dd] = *(const ulonglong2*)(sQ + ((size_t)(d * 2 + sq) * 32 + g) * 2);
            }
            #pragma unroll
            for (int fi = 0; fi < 8; ++fi) {
                const float* kb = sK + (8 * fq + fi) * 128 + pass * 64 + 4 * sq;
                #pragma unroll
                for (int dd = 0; dd < 8; ++dd) {
                    ulonglong2 kk = *(const ulonglong2*)(kb + dd * 8);
                    if (pass == 0 && dd == 0) {
                        lg0[fi] = mul2(qvh[0].x, kk.x);
                        lg1[fi] = mul2(qvh[0].y, kk.y);
                    } else {
                        lg0[fi] = fma2(qvh[dd].x, kk.x, lg0[fi]);
                        lg1[fi] = fma2(qvh[dd].y, kk.y, lg1[fi]);
                    }
                }
            }
        }

        // ---- accumulate logits sums (paired u128 RMW) + exp2 ----
        #pragma unroll
        for (int fi = 0; fi < 8; ++fi) {
            int idx = (((8 * fq + fi) * 2 + sq) * 32 + g) * 2;
            ulonglong2* p = (ulonglong2*)(sL + idx);
            ulonglong2 c = *p;
            c.x = add2(c.x, lg0[fi]);
            c.y = add2(c.y, lg1[fi]);
            *p = c;
            float a, bb;
            up2(lg0[fi], a, bb); lg0[fi] = pk2(ex2a(a), ex2a(bb));
            up2(lg1[fi], a, bb); lg1[fi] = pk2(ex2a(a), ex2a(bb));
        }

        __syncthreads();         // B2: logits done everywhere (sQ, sK dead)

        // ---- post unnormalized exps to eX ----
        #pragma unroll
        for (int fi = 0; fi < 8; ++fi) {
            int idx = (((8 * fq + fi) * 2 + sq) * 32 + g) * 2;
            ulonglong2 e; e.x = lg0[fi]; e.y = lg1[fi];
            *(ulonglong2*)(eX + idx) = e;
        }
        __syncthreads();         // B3: all exps posted

        // ---- x phase: own d-quarter (4 d) x (4 s), all 32 f; lazy normalize ----
        u64 xv0[4], xv1[4], sum0, sum1;
        {
            const int dbase = 4 * fq;
            #pragma unroll
            for (int f = 0; f < GQ; ++f) {
                ulonglong2 p2 = *(const ulonglong2*)(eX + ((f * 2 + sq) * 32 + g) * 2);
                const float* vb = sV + f * 128 + dbase * 8 + 4 * sq;
                if (f == 0) {
                    sum0 = p2.x; sum1 = p2.y;
                    #pragma unroll
                    for (int dd = 0; dd < 4; ++dd) {
                        ulonglong2 vv = *(const ulonglong2*)(vb + dd * 8);
                        xv0[dd] = mul2(p2.x, vv.x);
                        xv1[dd] = mul2(p2.y, vv.y);
                    }
                } else {
                    sum0 = add2(sum0, p2.x); sum1 = add2(sum1, p2.y);
                    #pragma unroll
                    for (int dd = 0; dd < 4; ++dd) {
                        ulonglong2 vv = *(const ulonglong2*)(vb + dd * 8);
                        xv0[dd] = fma2(p2.x, vv.x, xv0[dd]);
                        xv1[dd] = fma2(p2.y, vv.y, xv1[dd]);
                    }
                }
            }
        }
        float ra, rb;
        up2(sum0, ra, rb); const u64 rn0 = pk2(rcpa(ra), rcpa(rb));
        up2(sum1, ra, rb); const u64 rn1 = pk2(rcpa(ra), rcpa(rb));
        #pragma unroll
        for (int dd = 0; dd < 4; ++dd) {
            xv0[dd] = mul2(xv0[dd], rn0);
            xv1[dd] = mul2(xv1[dd], rn1);
        }

        // ---- accumulate attn sums for own f-quarter (re-read eX, normalize) ----
        #pragma unroll
        for (int fi = 0; fi < 8; ++fi) {
            int idx = (((8 * fq + fi) * 2 + sq) * 32 + g) * 2;
            ulonglong2 pe = *(const ulonglong2*)(eX + idx);
            ulonglong2* pa = (ulonglong2*)(sA + idx);
            ulonglong2 c = *pa;
            c.x = add2(c.x, mul2(pe.x, rn0));
            c.y = add2(c.y, mul2(pe.y, rn1));
            *pa = c;
        }
        __syncthreads();         // B4: eX + sV dead everywhere

        // prefetch K(h+1), V(h+1)
        if (h < NH - 1) {
            stage_async(sK, k + base + (size_t)(h + 1) * DK * SLEN, t);
            stage_async(sV, v + base + (size_t)(h + 1) * DK * SLEN, t);
            cp_commit();
        }

        // ---- stage x into xSt [(sp*16+d)*32+g] ----
        #pragma unroll
        for (int dd = 0; dd < 4; ++dd) {
            int d = 4 * fq + dd;
            xSt[((2 * sq + 0) * 16 + d) * 32 + g] = xv0[dd];
            xSt[((2 * sq + 1) * 16 + d) * 32 + g] = xv1[dd];
        }
        __syncthreads();         // B4.5: x staged

        // ---- cooperative coalesced STG (32B per (g,d) row, 2 lanes/row) ----
        #pragma unroll
        for (int i = 0; i < 4; ++i) {
            int u    = t + NT * i;        // 0..1023 units of 16B
            int r    = u >> 1;
            int half = u & 1;
            int dd   = r >> 5;
            int g2   = r & 31;
            u64 lo = xSt[((2 * half)     * 16 + dd) * 32 + g2];
            u64 hi = xSt[((2 * half + 1) * 16 + dd) * 32 + g2];
            float* dst = out + ((size_t)((b * GQ + g2) * HDIM) + (size_t)h * DK + dd) * SLEN
                             + (size_t)s0 + 4 * half;
            ulonglong2 val; val.x = lo; val.y = hi;
            *(ulonglong2*)dst = val;
        }
        __syncthreads();         // B5: xSt reads done -> sQ region writable

        if (qstager && h < NH - 1) sts_q(sQ, qA, qB, g, w4, sc);
    }

    // ---- writeout head means ----
    __syncthreads();
    const size_t AOFF = (size_t)B_SZ * GQ * HDIM * SLEN;       // 33554432
    const size_t LOFF = AOFF + (size_t)B_SZ * GQ * GQ * SLEN;  // 41943040
    const u64 cA = pk2(0.125f, 0.125f);
    const float lsc = 0.125f / L2E;                            // undo log2-domain
    const u64 cL = pk2(lsc, lsc);
    #pragma unroll
    for (int i = 0; i < 4; ++i) {
        int r  = t + NT * i;      // 0..1023
        int f  = r & 31;
        int gg = r >> 5;
        size_t o = ((size_t)(b * GQ + gg) * GQ + f) * SLEN + (size_t)s0;
        #pragma unroll
        for (int sp2 = 0; sp2 < 4; ++sp2) {
            int idx = ((f * 2 + (sp2 >> 1)) * 32 + gg) * 2 + (sp2 & 1);
            *(u64*)(out + AOFF + o + 2 * sp2) = mul2(sA[idx], cA);
            *(u64*)(out + LOFF + o + 2 * sp2) = mul2(sL[idx], cL);
        }
    }
}

extern "C" void kernel_launch(void* const* d_in, const int* in_sizes, int n_in,
                              void* d_out, int out_size)
{
    const float* q = (const float*)d_in[0];
    const float* k = (const float*)d_in[1];
    const float* v = (const float*)d_in[2];
    float* out = (float*)d_out;

    cudaFuncSetAttribute(sdpa_group_kernel,
                         cudaFuncAttributeMaxDynamicSharedMemorySize, SM_BYTES);

    dim3 grid(SLEN / STILE, B_SZ);
    sdpa_group_kernel<<<grid, NT, SM_BYTES>>>(q, k, v, out);
}